// round 17
// baseline (speedup 1.0000x reference)
#include <cuda_runtime.h>

// BinaryMaskEdgeSmoothing, R17: bulk-async producer (cp.async.bulk + mbarrier).
//
// R9-R16: DRAM pinned at 74% across every consumer/issue-side variation.
// Last untried subsystem: the producer. Replace 512 per-thread 16B cp.async
// per pair with two 4KB cp.async.bulk issued by ONE thread, completion via
// mbarrier expect_tx/complete_tx. Frees ~500 issue slots per pair and
// presents full 4KB contiguous requests to LTS/DRAM. 5-slot ring fully in
// flight: 40KB/block, 200KB/SM.
//
// Rule (verified rel_err = 0.0 since R4; binary inputs make sum9 and
// gsum = 16*blur exact small ints in f32):
//     out = (gsum >= 9) || (gsum == 8 && cen == 1 && sum9 >= 4)
// via: qual = 6*cen + sum9; adj = qual>9.5 ? 0.6 : 0; out = gsum+adj > 8.5.

#define IMG_W   1024
#define IMG_H   1024
#define RPB     16                // output rows per block
#define THREADS 256               // 4 cols per thread
#define NPAIRS  ((RPB + 2) / 2)   // 9 input pairs: rows r0-1 .. r0+RPB
#define STAGES  5                 // ring slots -> 40KB smem
#define ROW_B   (IMG_W * 4)
#define PAIR_B  (2 * ROW_B)       // 8192

struct Sums { float t[4], g[4]; };

__device__ __forceinline__ void mbar_init(unsigned mb, unsigned cnt) {
    asm volatile("mbarrier.init.shared.b64 [%0], %1;" :: "r"(mb), "r"(cnt)
                 : "memory");
}
__device__ __forceinline__ void mbar_expect_tx(unsigned mb, unsigned bytes) {
    asm volatile("mbarrier.arrive.expect_tx.shared.b64 _, [%0], %1;"
                 :: "r"(mb), "r"(bytes) : "memory");
}
__device__ __forceinline__ void mbar_wait(unsigned mb, unsigned phase) {
    asm volatile(
        "{\n\t.reg .pred P;\n\t"
        "W_%=:\n\t"
        "mbarrier.try_wait.parity.acquire.cta.shared::cta.b64 P, [%0], %1;\n\t"
        "@P bra D_%=;\n\t"
        "bra W_%=;\n\t"
        "D_%=:\n\t}"
        :: "r"(mb), "r"(phase) : "memory");
}
__device__ __forceinline__ void bulk_cp(unsigned dst, const float* src,
                                        unsigned bytes, unsigned mb) {
    asm volatile(
        "cp.async.bulk.shared::cta.global.mbarrier::complete_tx::bytes "
        "[%0], [%1], %2, [%3];"
        :: "r"(dst), "l"(src), "r"(bytes), "r"(mb) : "memory");
}

__device__ __forceinline__ Sums make_sums(const float* __restrict__ rp,
                                          int x0, bool hl, bool hr) {
    float4 v = *reinterpret_cast<const float4*>(rp + x0);     // LDS.128
    float e0 = 0.f, e5 = 0.f;
    if (hl) { float2 L = *reinterpret_cast<const float2*>(rp + x0 - 2); e0 = L.y; }
    if (hr) { float2 R = *reinterpret_cast<const float2*>(rp + x0 + 4); e5 = R.x; }
    Sums s;
    s.t[0] = e0  + v.x + v.y;  s.g[0] = s.t[0] + v.x;
    s.t[1] = v.x + v.y + v.z;  s.g[1] = s.t[1] + v.y;
    s.t[2] = v.y + v.z + v.w;  s.g[2] = s.t[2] + v.z;
    s.t[3] = v.z + v.w + e5;   s.g[3] = s.t[3] + v.w;
    return s;
}

__device__ __forceinline__ Sums zero_sums() {
    Sums s;
    #pragma unroll
    for (int j = 0; j < 4; ++j) { s.t[j] = 0.f; s.g[j] = 0.f; }
    return s;
}

__device__ __forceinline__ float4 compute_row(const Sums& A, const Sums& B,
                                              const Sums& C) {
    float res[4];
    #pragma unroll
    for (int j = 0; j < 4; ++j) {
        float sum9 = A.t[j] + B.t[j] + C.t[j];            // 0..9 exact
        float gsum = fmaf(2.f, B.g[j], A.g[j] + C.g[j]);  // 0..16 exact
        float cen  = B.g[j] - B.t[j];                     // 0 or 1
        float qual = fmaf(6.f, cen, sum9);                // >=10 <=> qualify
        float adj  = (qual > 9.5f) ? 0.6f : 0.f;
        res[j] = (gsum + adj > 8.5f) ? 1.f : 0.f;
    }
    return make_float4(res[0], res[1], res[2], res[3]);
}

__global__ void __launch_bounds__(THREADS, 5)
edge_smooth_kernel(const float* __restrict__ in, float* __restrict__ out) {
    __shared__ float buf[STAGES][2][IMG_W];               // 40KB ring
    __shared__ alignas(8) unsigned long long mbar[STAGES];

    const int img = blockIdx.y;
    const int r0  = blockIdx.x * RPB;
    const int tid = threadIdx.x;
    const int x0  = tid * 4;
    const bool hl = (x0 > 0);
    const bool hr = (x0 + 4 < IMG_W);

    const float* gimg = in + (size_t)img * IMG_H * IMG_W;     // block row base
    float*       po   = out + ((size_t)img * IMG_H + r0) * IMG_W + x0;

    unsigned sbuf = (unsigned)__cvta_generic_to_shared(&buf[0][0][0]);
    unsigned smb  = (unsigned)__cvta_generic_to_shared(&mbar[0]);

    if (tid == 0) {
        #pragma unroll
        for (int s = 0; s < STAGES; ++s) mbar_init(smb + 8u * s, 1u);
    }
    __syncthreads();

    // Producer: tid0 issues pair p (rows r0-1+2p, r0+2p; clamped — over-
    // fetched edge rows never consumed) as two 4KB bulk copies.
    auto issue_pair = [&](int p) {
        if (tid == 0) {
            int row0 = min(max(r0 - 1 + 2 * p, 0), IMG_H - 1);
            int row1 = min(r0 + 2 * p, IMG_H - 1);
            unsigned mb  = smb + 8u * (unsigned)(p % STAGES);
            unsigned dst = sbuf + (unsigned)(p % STAGES) * PAIR_B;
            mbar_expect_tx(mb, PAIR_B);
            bulk_cp(dst,         gimg + (size_t)row0 * IMG_W, ROW_B, mb);
            bulk_cp(dst + ROW_B, gimg + (size_t)row1 * IMG_W, ROW_B, mb);
        }
    };

    // Prologue: all 5 slots in flight.
    issue_pair(0); issue_pair(1); issue_pair(2); issue_pair(3); issue_pair(4);

    // Prime (pair 0, slot 0, phase 0): A = row r0-1 (zeros at top), B = r0.
    mbar_wait(smb + 0u, 0u);
    Sums A = (r0 > 0) ? make_sums(buf[0][0], x0, hl, hr) : zero_sums();
    Sums B = make_sums(buf[0][1], x0, hl, hr);

    // Steady state: consume pairs 1..7; issue pairs 5..8 into freed slots.
    // Slot reuse: pair i+4 -> slot (i-1)%5, sealed by this iter's barrier.
    #pragma unroll
    for (int i = 1; i <= NPAIRS - 2; ++i) {
        __syncthreads();                       // seal pair i-1 consumption
        if (i + 4 < NPAIRS) issue_pair(i + 4);

        mbar_wait(smb + 8u * (unsigned)(i % STAGES), (unsigned)(i / STAGES));

        const int s = i % STAGES;
        Sums C = make_sums(buf[s][0], x0, hl, hr);
        Sums D = make_sums(buf[s][1], x0, hl, hr);

        __stcs(reinterpret_cast<float4*>(po + (size_t)(2 * i - 2) * IMG_W),
               compute_row(A, B, C));
        __stcs(reinterpret_cast<float4*>(po + (size_t)(2 * i - 1) * IMG_W),
               compute_row(B, C, D));

        A = C; B = D;
    }

    // Epilogue (pair 8, slot 3, phase 1): bottom row zeros at image bottom.
    mbar_wait(smb + 8u * ((NPAIRS - 1) % STAGES), (unsigned)((NPAIRS - 1) / STAGES));
    {
        const int s = (NPAIRS - 1) % STAGES;
        Sums C = make_sums(buf[s][0], x0, hl, hr);
        Sums D = (r0 + RPB < IMG_H) ? make_sums(buf[s][1], x0, hl, hr)
                                    : zero_sums();
        __stcs(reinterpret_cast<float4*>(po + (size_t)(RPB - 2) * IMG_W),
               compute_row(A, B, C));
        __stcs(reinterpret_cast<float4*>(po + (size_t)(RPB - 1) * IMG_W),
               compute_row(B, C, D));
    }
}

extern "C" void kernel_launch(void* const* d_in, const int* in_sizes, int n_in,
                              void* d_out, int out_size) {
    const float* mask = (const float*)d_in[0];   // (B,C,1024,1024) f32
    float*       out  = (float*)d_out;

    int n_imgs = in_sizes[0] / (IMG_H * IMG_W);  // B*C

    dim3 grid(IMG_H / RPB, n_imgs);
    dim3 block(THREADS);
    edge_smooth_kernel<<<grid, block>>>(mask, out);
}